// round 4
// baseline (speedup 1.0000x reference)
#include <cuda_runtime.h>
#include <cstdint>

#define B_   256
#define T_   2048
#define IN_  128
#define H_   64
#define G_   256   // 4*H

// Scratch (allocation-free rule: static __device__ arrays)
__device__ float g_xp[(size_t)B_ * T_ * G_];   // precomputed x@W_ih1^T + b_ih1 + b_hh1
__device__ float g_Wt[IN_ * G_];               // W_ih1 transposed: [k][g]

typedef unsigned long long u64;

// ---------------- helpers ----------------
__device__ __forceinline__ void ffma2(u64& d, u64 a, u64 b) {
    asm("fma.rn.f32x2 %0, %1, %2, %0;" : "+l"(d) : "l"(a), "l"(b));
}
__device__ __forceinline__ float2 unpk(u64 p) {
    float2 r;
    asm("mov.b64 {%0, %1}, %2;" : "=f"(r.x), "=f"(r.y) : "l"(p));
    return r;
}
__device__ __forceinline__ u64 dup2(float a) {
    u64 r;
    asm("mov.b64 %0, {%1, %1};" : "=l"(r) : "f"(a));
    return r;
}
__device__ __forceinline__ float sigf(float x) {
    return __fdividef(1.0f, 1.0f + __expf(-x));
}
__device__ __forceinline__ float tanhf_(float x) {
    float a = fabsf(x);
    float e = __expf(2.0f * a);                 // inf-safe
    float r = 1.0f - __fdividef(2.0f, e + 1.0f);
    return copysignf(r, x);
}

// ---------------- kernel 1: transpose W_ih1 into k-major ----------------
__global__ void wt_kernel(const float* __restrict__ W) {
    int i = blockIdx.x * 256 + threadIdx.x;    // 32768 elems
    int n = i >> 7;
    int k = i & 127;
    g_Wt[k * G_ + n] = W[n * IN_ + k];
}

// ---------------- kernel 2: xp = x @ W_ih1^T + b_ih1 + b_hh1 ----------------
__global__ __launch_bounds__(256) void xp_gemm(const float* __restrict__ x,
                                               const float* __restrict__ bih,
                                               const float* __restrict__ bhh) {
    __shared__ float Xs[64][128];              // 32 KB
    int tid = threadIdx.x;
    size_t mbase = (size_t)blockIdx.x * 64;
    int nbase = blockIdx.y * 64;

    const float* xg = x + mbase * IN_;
#pragma unroll
    for (int i = 0; i < 8; i++) {
        int idx = tid + i * 256;
        int m = idx >> 5, k4 = (idx & 31) << 2;
        *(float4*)&Xs[m][k4] = *(const float4*)(xg + m * IN_ + k4);
    }
    __syncthreads();

    int tx = tid & 15, ty = tid >> 4;
    int n0 = nbase + tx * 4;
    int m0 = ty * 4;

    u64 acc[4][2];
#pragma unroll
    for (int i = 0; i < 4; i++) { acc[i][0] = 0ull; acc[i][1] = 0ull; }

    const float* wt = g_Wt + n0;
#pragma unroll 8
    for (int k = 0; k < IN_; k++) {
        ulonglong2 bb = *(const ulonglong2*)(wt + k * G_);
#pragma unroll
        for (int i = 0; i < 4; i++) {
            u64 ap = dup2(Xs[m0 + i][k]);
            ffma2(acc[i][0], ap, bb.x);
            ffma2(acc[i][1], ap, bb.y);
        }
    }

    float4 bs;
    bs.x = bih[n0 + 0] + bhh[n0 + 0];
    bs.y = bih[n0 + 1] + bhh[n0 + 1];
    bs.z = bih[n0 + 2] + bhh[n0 + 2];
    bs.w = bih[n0 + 3] + bhh[n0 + 3];
#pragma unroll
    for (int i = 0; i < 4; i++) {
        float2 p0 = unpk(acc[i][0]);
        float2 p1 = unpk(acc[i][1]);
        float4 o = make_float4(p0.x + bs.x, p0.y + bs.y, p1.x + bs.z, p1.y + bs.w);
        *(float4*)(g_xp + (mbase + m0 + i) * G_ + n0) = o;
    }
}

// ---------------- kernel 3: fused 2-layer LSTM recurrence + output head ----------------
// 128 CTAs x 512 threads, 2 batch rows per CTA.
// Thread tid: s = tid&3 (k-split), q = tid>>2 (gate pair: gates 2q, 2q+1).
//   Layer-1 dot: k in [16s, 16s+16)  over h1 (64).
//   Layer-2 dot: kcat in [32s, 32s+32) over concat [h1new(64); h2prev(64)].
// Weights/thread: 2*16 + 2*32 = 96 floats = 48 u64 (96 regs). Total fits 128-reg cap.
// Gate partials combined with 2-level shfl_xor butterfly over the s lanes.
// tid<128: activation threads (1 warp/SMSP). tid in [128,256): xp prefetchers.
// 3 barriers/step; U2 overlaps the next step's P1.
__global__ __launch_bounds__(512, 1) void lstm_rec(
    const float* __restrict__ Whh1, const float* __restrict__ Wih2,
    const float* __restrict__ Whh2, const float* __restrict__ bih2,
    const float* __restrict__ bhh2, const float* __restrict__ Wout,
    const float* __restrict__ bout, float* __restrict__ out) {
    __shared__ float h1s[2][64];      // [row][unit]
    __shared__ float h2s[2][64];
    __shared__ float ga[2][256];      // [row][gate]
    __shared__ float gb[2][256];
    __shared__ float xbuf[2][2][256]; // [t&1][row][gate]
    __shared__ float b2s[256];        // bias2 sums
    __shared__ float wos[64];         // Wout
    __shared__ float red[4];

    int tid = threadIdx.x;
    int s = tid & 3, q = tid >> 2;
    int g0 = q * 2;

    // ---- weights into registers ----
    u64 w1[2][8];     // [gate][k-pair], k in [16s, 16s+16)
    u64 w2[2][16];    // [gate][kc-pair], kcat in [32s, 32s+32)
#pragma unroll
    for (int g = 0; g < 2; g++) {
        const u64* p1 = (const u64*)(Whh1 + (g0 + g) * 64 + s * 16);
#pragma unroll
        for (int j = 0; j < 8; j++) w1[g][j] = p1[j];
        const float* b2 = (s < 2) ? (Wih2 + (g0 + g) * 64 + s * 32)
                                  : (Whh2 + (g0 + g) * 64 + (s - 2) * 32);
        const u64* p2 = (const u64*)b2;
#pragma unroll
        for (int j = 0; j < 16; j++) w2[g][j] = p2[j];
    }
    if (tid < 256) b2s[tid] = bih2[tid] + bhh2[tid];
    if (tid < 64) wos[tid] = Wout[tid];

    int ur = tid >> 6, uu = tid & 63;          // activation threads (tid<128)
    float bo = bout[0];
    float c1v = 0.0f, c2v = 0.0f;

    int b0 = blockIdx.x * 2;
    // prefetch threads (tid in [128,256)): i -> (row pr, 4 gates at pc)
    int pi = tid - 128;
    int pr = pi >> 6, pc = (pi & 63) * 4;
    const float* xpp = g_xp + ((size_t)(b0 + pr) * T_) * G_ + pc;

    if (tid < 128) { ((float*)h1s)[tid] = 0.0f; ((float*)h2s)[tid] = 0.0f; }
    if (tid >= 128 && tid < 256) {             // preload xbuf for t=0
        float4 xv0 = *(const float4*)xpp;
        *(float4*)&xbuf[0][pr][pc] = xv0;
    }
    __syncthreads();

    for (int t = 0; t < T_; t++) {
        // prefetch next step's xp (consumed in U1 of t+1)
        float4 xv = make_float4(0, 0, 0, 0);
        if (tid >= 128 && tid < 256 && t + 1 < T_)
            xv = *(const float4*)(xpp + (size_t)(t + 1) * G_);

        // ---- P1: layer-1 recurrent gate partial dots ----
        u64 acc[4];                            // [g*2 + row]
#pragma unroll
        for (int i = 0; i < 4; i++) acc[i] = 0ull;
        {
            const ulonglong2* hA = (const ulonglong2*)&h1s[0][s * 16];
            const ulonglong2* hB = (const ulonglong2*)&h1s[1][s * 16];
#pragma unroll
            for (int j = 0; j < 4; j++) {
                ulonglong2 u0 = hA[j];
                ulonglong2 u1 = hB[j];
#pragma unroll
                for (int g = 0; g < 2; g++) {
                    ffma2(acc[2 * g + 0], w1[g][2 * j], u0.x);
                    ffma2(acc[2 * g + 0], w1[g][2 * j + 1], u0.y);
                    ffma2(acc[2 * g + 1], w1[g][2 * j], u1.x);
                    ffma2(acc[2 * g + 1], w1[g][2 * j + 1], u1.y);
                }
            }
        }
        float v[4];
#pragma unroll
        for (int i = 0; i < 4; i++) {
            float2 f = unpk(acc[i]);
            v[i] = f.x + f.y;
            v[i] += __shfl_xor_sync(0xffffffffu, v[i], 1);
            v[i] += __shfl_xor_sync(0xffffffffu, v[i], 2);
        }
        if (s == 0) {
            *(float2*)&ga[0][g0] = make_float2(v[0], v[2]);
            *(float2*)&ga[1][g0] = make_float2(v[1], v[3]);
        }
        __syncthreads();                       // B1

        if (tid < 2 && t > 0) {                // lagged output write
            float r = red[2 * tid] + red[2 * tid + 1] + bo;
            r = fminf(fmaxf(r, 0.0f), 1.0f);
            out[(size_t)(b0 + tid) * T_ + (t - 1)] = r;
        }

        // ---- U1: layer-1 activations ----
        if (tid < 128) {
            const float* xb = &xbuf[t & 1][ur][0];
            float iv = sigf(ga[ur][uu] + xb[uu]);
            float fv = sigf(ga[ur][64 + uu] + xb[64 + uu]);
            float gv = tanhf_(ga[ur][128 + uu] + xb[128 + uu]);
            float ov = sigf(ga[ur][192 + uu] + xb[192 + uu]);
            c1v = fv * c1v + iv * gv;
            h1s[ur][uu] = ov * tanhf_(c1v);
        }
        __syncthreads();                       // B2

        // ---- P2: layer-2 gate partial dots over concat [h1new; h2prev] ----
#pragma unroll
        for (int i = 0; i < 4; i++) acc[i] = 0ull;
        {
            const ulonglong2* pA;
            const ulonglong2* pB;
            if (s < 2) {
                pA = (const ulonglong2*)&h1s[0][s * 32];
                pB = (const ulonglong2*)&h1s[1][s * 32];
            } else {
                pA = (const ulonglong2*)&h2s[0][(s - 2) * 32];
                pB = (const ulonglong2*)&h2s[1][(s - 2) * 32];
            }
#pragma unroll
            for (int j = 0; j < 8; j++) {
                ulonglong2 u0 = pA[j];
                ulonglong2 u1 = pB[j];
#pragma unroll
                for (int g = 0; g < 2; g++) {
                    ffma2(acc[2 * g + 0], w2[g][2 * j], u0.x);
                    ffma2(acc[2 * g + 0], w2[g][2 * j + 1], u0.y);
                    ffma2(acc[2 * g + 1], w2[g][2 * j], u1.x);
                    ffma2(acc[2 * g + 1], w2[g][2 * j + 1], u1.y);
                }
            }
        }
#pragma unroll
        for (int i = 0; i < 4; i++) {
            float2 f = unpk(acc[i]);
            v[i] = f.x + f.y;
            v[i] += __shfl_xor_sync(0xffffffffu, v[i], 1);
            v[i] += __shfl_xor_sync(0xffffffffu, v[i], 2);
        }
        if (s == 0) {
            *(float2*)&gb[0][g0] = make_float2(v[0], v[2]);
            *(float2*)&gb[1][g0] = make_float2(v[1], v[3]);
        }
        __syncthreads();                       // B3

        // stash prefetched xp (read by U1 of t+1, after next B1)
        if (tid >= 128 && tid < 256 && t + 1 < T_)
            *(float4*)&xbuf[(t + 1) & 1][pr][pc] = xv;

        // ---- U2: layer-2 activations + output-head partials (no barrier;
        //          overlaps the next iteration's P1 in the other warps) ----
        if (tid < 128) {
            float iv = sigf(gb[ur][uu] + b2s[uu]);
            float fv = sigf(gb[ur][64 + uu] + b2s[64 + uu]);
            float gv = tanhf_(gb[ur][128 + uu] + b2s[128 + uu]);
            float ov = sigf(gb[ur][192 + uu] + b2s[192 + uu]);
            c2v = fv * c2v + iv * gv;
            float h2v = ov * tanhf_(c2v);
            h2s[ur][uu] = h2v;
            float p = wos[uu] * h2v;
#pragma unroll
            for (int off = 16; off > 0; off >>= 1)
                p += __shfl_xor_sync(0xffffffffu, p, off);
            if ((tid & 31) == 0) red[tid >> 5] = p;
        }
    }

    __syncthreads();
    if (tid < 2) {                             // final timestep's output
        float r = red[2 * tid] + red[2 * tid + 1] + bo;
        r = fminf(fmaxf(r, 0.0f), 1.0f);
        out[(size_t)(b0 + tid) * T_ + (T_ - 1)] = r;
    }
}

// ---------------- launch ----------------
extern "C" void kernel_launch(void* const* d_in, const int* in_sizes, int n_in,
                              void* d_out, int out_size) {
    const float* x    = (const float*)d_in[0];
    const float* Wih1 = (const float*)d_in[1];
    const float* Whh1 = (const float*)d_in[2];
    const float* bih1 = (const float*)d_in[3];
    const float* bhh1 = (const float*)d_in[4];
    const float* Wih2 = (const float*)d_in[5];
    const float* Whh2 = (const float*)d_in[6];
    const float* bih2 = (const float*)d_in[7];
    const float* bhh2 = (const float*)d_in[8];
    const float* Wout = (const float*)d_in[9];
    const float* bout = (const float*)d_in[10];
    float* out = (float*)d_out;

    wt_kernel<<<128, 256>>>(Wih1);
    xp_gemm<<<dim3((B_ * T_) / 64, G_ / 64), 256>>>(x, bih1, bhh1);
    lstm_rec<<<128, 512>>>(Whh1, Wih2, Whh2, bih2, bhh2, Wout, bout, out);
    (void)in_sizes; (void)n_in; (void)out_size;
}